// round 6
// baseline (speedup 1.0000x reference)
#include <cuda_runtime.h>
#include <cuda_fp16.h>
#include <cstdint>
#include <cstddef>

#define Bb 16
#define Tt 128
#define Dd 256
#define CLUSTER 4
#define HCOLS 128            // columns per CTA (one layer, half the columns)
#define NTHREADS 512
#define NDPT 64              // d-elements per thread
#define NPAIR 32             // half2 pairs per thread

__device__ __forceinline__ uint32_t my_cluster_rank() {
    uint32_t r; asm("mov.u32 %0, %%cluster_ctarank;" : "=r"(r)); return r;
}
__device__ __forceinline__ void cluster_sync_() {
    asm volatile("barrier.cluster.arrive.aligned;" ::: "memory");
    asm volatile("barrier.cluster.wait.aligned;" ::: "memory");
}
__device__ __forceinline__ uint32_t mapa_u32(uint32_t laddr, uint32_t rank) {
    uint32_t r;
    asm("mapa.shared::cluster.u32 %0, %1, %2;" : "=r"(r) : "r"(laddr), "r"(rank));
    return r;
}
__device__ __forceinline__ void st_remote(uint32_t addr, float v) {
    asm volatile("st.shared::cluster.f32 [%0], %1;" :: "r"(addr), "f"(v) : "memory");
}
__device__ __forceinline__ void mb_init(uint32_t addr, uint32_t count) {
    asm volatile("mbarrier.init.shared.b64 [%0], %1;" :: "r"(addr), "r"(count) : "memory");
}
// Remote arrive on a peer CTA's mbarrier (release, cluster scope).
__device__ __forceinline__ void mb_arrive_remote(uint32_t raddr) {
    asm volatile("mbarrier.arrive.release.cluster.shared::cluster.b64 _, [%0];"
                 :: "r"(raddr) : "memory");
}
// Sleep-based parity wait with cluster-scope acquire (peer stores visible after).
__device__ __forceinline__ void mb_wait(uint32_t addr, uint32_t parity) {
    uint32_t done;
    asm volatile(
        "{\n\t.reg .pred p;\n\t"
        "mbarrier.try_wait.parity.acquire.cluster.shared::cta.b64 p, [%1], %2;\n\t"
        "selp.b32 %0, 1, 0, p;\n\t}"
        : "=r"(done) : "r"(addr), "r"(parity) : "memory");
    while (!done) {
        asm volatile(
            "{\n\t.reg .pred p;\n\t"
            "mbarrier.try_wait.parity.acquire.cluster.shared::cta.b64 p, [%1], %2, 0x989680;\n\t"
            "selp.b32 %0, 1, 0, p;\n\t}"
            : "=r"(done) : "r"(addr), "r"(parity) : "memory");
    }
}
__device__ __forceinline__ float tanh_ap(float x) {
    float y; asm("tanh.approx.f32 %0, %1;" : "=f"(y) : "f"(x)); return y;
}
__device__ __forceinline__ float grp4_sum(float v) {
    v += __shfl_xor_sync(0xffffffffu, v, 1);
    v += __shfl_xor_sync(0xffffffffu, v, 2);
    return v;
}

__global__ void __launch_bounds__(NTHREADS, 1) __cluster_dims__(CLUSTER, 1, 1)
plastic_kernel(const int* __restrict__ x, const float* __restrict__ emb,
               const float* __restrict__ ws, const float* __restrict__ alphas,
               const float* __restrict__ etas, float* __restrict__ out)
{
    __shared__ __align__(16) float ybuf[4][Dd];     // my layer's y, slot = step & 3
    __shared__ __align__(16) float y0h[4][HCOLS];   // L1: incoming y0 own-half ring
    __shared__ __align__(16) float stage[64 * HCOLS];
    __shared__ int   xtok[Tt];
    __shared__ float redbuf[8];
    __shared__ __align__(8) unsigned long long mb_partner[2], mb_y0[4], mb_credit[8];

    const int tid     = threadIdx.x;
    const int batch   = blockIdx.x >> 2;
    const int rank    = (int)my_cluster_rank();
    const int layer   = rank >> 1;
    const int half    = rank & 1;
    const int col_off = half * HCOLS;
    const int partner = rank ^ 1;
    const int col     = tid >> 2;           // 0..127
    const int colg    = col_off + col;
    const int dgrp    = tid & 3;            // 0..3
    const int dbase   = dgrp * NDPT;
    const int wid     = tid >> 5, lane = tid & 31;

    // init shared
    for (int i = tid; i < 4 * Dd; i += NTHREADS) ybuf[i >> 8][i & 255] = 0.f;
    for (int i = tid; i < 4 * HCOLS; i += NTHREADS) y0h[i >> 7][i & 127] = 0.f;
    if (tid < Tt) xtok[tid] = x[batch * Tt + tid];
    if (tid == 0) {
        mb_init((uint32_t)__cvta_generic_to_shared(&mb_partner[0]), 1);
        mb_init((uint32_t)__cvta_generic_to_shared(&mb_partner[1]), 1);
        for (int s = 0; s < 4; ++s)
            mb_init((uint32_t)__cvta_generic_to_shared(&mb_y0[s]), 1);
        for (int s = 0; s < 8; ++s)
            mb_init((uint32_t)__cvta_generic_to_shared(&mb_credit[s]), 1);
    }
    __syncthreads();

    const float eta = etas[layer];
    const float om  = 1.0f - eta;
    const __half2 om2 = __float2half2_rn(om);

    // fp16-packed per-thread weight state
    __half2 w2[NPAIR], a2[NPAIR], h2[NPAIR];
#pragma unroll
    for (int i = 0; i < NPAIR; i++) h2[i] = __float2half2_rn(0.f);

    const float* wsrc = ws     + (size_t)layer * Dd * Dd;
    const float* asrc = alphas + (size_t)layer * Dd * Dd;
#define STAGE_H2(dst, gptr)                                                  \
    for (int c = 0; c < 4; ++c) {                                            \
        __syncthreads();                                                     \
        for (int k = 0; k < 16; ++k) {                                       \
            int idx = tid + k * NTHREADS;                                    \
            int dd = idx >> 7, j = idx & 127;                                \
            stage[idx] = (gptr)[(size_t)(c * 64 + dd) * Dd + col_off + j];   \
        }                                                                    \
        __syncthreads();                                                     \
        if (dgrp == c) {                                                     \
            _Pragma("unroll")                                                \
            for (int p = 0; p < NPAIR; ++p)                                  \
                dst[p] = __floats2half2_rn(stage[(2 * p) * HCOLS + col],     \
                                           stage[(2 * p + 1) * HCOLS + col]);\
        }                                                                    \
    }
    STAGE_H2(w2, wsrc)
    STAGE_H2(a2, asrc)
    __syncthreads();

    // per-target-rank smem address deltas (uniform per rank)
    const uint32_t base0 = (uint32_t)__cvta_generic_to_shared(&ybuf[0][0]);
    const uint32_t del_partner = mapa_u32(base0, (uint32_t)partner) - base0;
    const uint32_t del_inter   = (layer == 0)
        ? (mapa_u32(base0, (uint32_t)(rank + 2)) - base0)    // L0 -> its L1
        : (mapa_u32(base0, (uint32_t)(rank - 2)) - base0);   // L1 -> its L0
    const uint32_t mbp0 = (uint32_t)__cvta_generic_to_shared(&mb_partner[0]);
    const uint32_t mby0 = (uint32_t)__cvta_generic_to_shared(&mb_y0[0]);
    const uint32_t mbc0 = (uint32_t)__cvta_generic_to_shared(&mb_credit[0]);

    cluster_sync_();   // buffers zeroed + barriers armed everywhere

    float* const outB = out + (size_t)batch * Tt * Dd;
    float embreg = (layer == 0) ? __ldg(&emb[(size_t)xtok[0] * Dd + colg]) : 0.f;

    for (int t = 0; t < Tt; ++t) {
        // ---- waits (sleep-based, no spin traffic) ----
        if (t >= 1)
            mb_wait(mbp0 + 8u * (uint32_t)((t - 1) & 1), (uint32_t)(((t - 1) >> 1) & 1));
        if (layer == 1)
            mb_wait(mby0 + 8u * (uint32_t)(t & 3), (uint32_t)((t >> 2) & 1));
        else if (t >= 4)
            mb_wait(mbc0 + 8u * (uint32_t)((t - 4) & 7), (uint32_t)(((t - 4) >> 3) & 1));

        const int sp = (t + 3) & 3;           // slot of y(t-1)
        const int sc = t & 3;                 // slot of y(t)

        // ---- dot: sum_d yin[d] * (a*h + w)[d, colg] ----
        const float* yin = ybuf[sp] + dbase;
        float s0 = 0.f, s1 = 0.f, s2 = 0.f, s3 = 0.f;
#pragma unroll
        for (int i = 0; i < NPAIR; i += 2) {
            float4 yv = *reinterpret_cast<const float4*>(yin + 2 * i);
            float2 t0 = __half22float2(__hfma2(a2[i],     h2[i],     w2[i]));
            float2 t1 = __half22float2(__hfma2(a2[i + 1], h2[i + 1], w2[i + 1]));
            s0 = fmaf(yv.x, t0.x, s0);
            s1 = fmaf(yv.y, t0.y, s1);
            s2 = fmaf(yv.z, t1.x, s2);
            s3 = fmaf(yv.w, t1.y, s3);
        }
        float acc = grp4_sum((s0 + s1) + (s2 + s3));
        const float inp = (layer == 0) ? embreg : y0h[sc][col];
        const float y = tanh_ap(acc + inp);

        // ---- push y(t): own-half locally + to partner; L0 also to its L1 ----
        const uint32_t la = (uint32_t)__cvta_generic_to_shared(&ybuf[sc][colg]);
        if (dgrp == 1) ybuf[sc][colg] = y;
        if (dgrp == 0) st_remote(la + del_partner, y);
        if (dgrp == 2 && layer == 0) {
            const uint32_t l0a = (uint32_t)__cvta_generic_to_shared(&y0h[sc][col]);
            st_remote(l0a + del_inter, y);
        }
        __syncthreads();   // all y stores issued before the release-arrives

        if (tid == 0)
            mb_arrive_remote(mbp0 + 8u * (uint32_t)(t & 1) + del_partner);
        if (tid == 32) {
            if (layer == 0) mb_arrive_remote(mby0 + 8u * (uint32_t)(t & 3) + del_inter);
            else            mb_arrive_remote(mbc0 + 8u * (uint32_t)(t & 7) + del_inter);
        }

        // ---- deferred work (overlaps arrive/data flight) ----
        {   // hebb: h = om*h + (eta*y) * yin
            const float ey = eta * y;
#pragma unroll
            for (int i = 0; i < NPAIR; i += 2) {
                float4 yv = *reinterpret_cast<const float4*>(yin + 2 * i);
                h2[i]     = __hfma2(h2[i],     om2, __floats2half2_rn(yv.x * ey, yv.y * ey));
                h2[i + 1] = __hfma2(h2[i + 1], om2, __floats2half2_rn(yv.z * ey, yv.w * ey));
            }
        }
        if (layer == 0) {
            if (t + 1 < Tt) embreg = __ldg(&emb[(size_t)xtok[t + 1] * Dd + colg]);
        } else if (t >= 1) {
            // out(t-1) = softmax(sigmoid(y1(t-1))); y1(t-1) full in ybuf[sp]
            float ex = 0.f;
            if (tid < Dd) {
                float yv = ybuf[sp][tid];
                float s = __fdividef(1.0f, 1.0f + __expf(-yv));
                ex = __expf(s);
            }
            float wsum = ex;
#pragma unroll
            for (int o = 16; o >= 1; o >>= 1)
                wsum += __shfl_xor_sync(0xffffffffu, wsum, o);
            if (wid < 8 && lane == 0) redbuf[wid] = wsum;
            __syncthreads();
            float tot = 0.f;
#pragma unroll
            for (int k = 0; k < 8; k++) tot += redbuf[k];
            if (tid >= col_off && tid < col_off + HCOLS)
                outB[(size_t)(t - 1) * Dd + tid] = __fdividef(ex, tot);
        }
    }

    // ---- epilogue: L1 writes out(Tt-1) after partner's final arrive (#127) ----
    if (layer == 1) {
        mb_wait(mbp0 + 8u * (uint32_t)((Tt - 1) & 1), (uint32_t)(((Tt - 1) >> 1) & 1));
        const float* ys = ybuf[(Tt - 1) & 3];
        float ex = 0.f;
        if (tid < Dd) {
            float yv = ys[tid];
            float s = __fdividef(1.0f, 1.0f + __expf(-yv));
            ex = __expf(s);
        }
        float wsum = ex;
#pragma unroll
        for (int o = 16; o >= 1; o >>= 1)
            wsum += __shfl_xor_sync(0xffffffffu, wsum, o);
        if (wid < 8 && lane == 0) redbuf[wid] = wsum;
        __syncthreads();
        float tot = 0.f;
#pragma unroll
        for (int k = 0; k < 8; k++) tot += redbuf[k];
        if (tid >= col_off && tid < col_off + HCOLS)
            outB[(size_t)(Tt - 1) * Dd + tid] = __fdividef(ex, tot);
    }

    cluster_sync_();   // keep smem alive until all peers are done
}

extern "C" void kernel_launch(void* const* d_in, const int* in_sizes, int n_in,
                              void* d_out, int out_size) {
    const int*   x      = (const int*)d_in[0];
    const float* emb    = (const float*)d_in[1];
    const float* ws     = (const float*)d_in[2];
    const float* alphas = (const float*)d_in[3];
    const float* etas   = (const float*)d_in[4];
    plastic_kernel<<<Bb * CLUSTER, NTHREADS>>>(x, emb, ws, alphas, etas, (float*)d_out);
}

// round 7
// speedup vs baseline: 1.3262x; 1.3262x over previous
#include <cuda_runtime.h>
#include <cuda_fp16.h>
#include <cstdint>
#include <cstddef>

#define Bb 16
#define Tt 128
#define Dd 256
#define HCOLS 128
#define NTHREADS 512
#define YROW 280                 // 4 chunks of 72 floats (64 data + 8 pad)

#define OFF_W    0
#define SZ_W     (16 * NTHREADS * 8)       // 65536: fp16 weights, per-thread chunks
#define OFF_YB   (OFF_W + SZ_W)
#define SZ_YB    (2 * 4 * YROW * 4)        // 8960
#define OFF_Y0H  (OFF_YB + SZ_YB)
#define SZ_Y0H   (2 * 4 * HCOLS * 4)       // 4096
#define OFF_XT   (OFF_Y0H + SZ_Y0H)
#define SZ_XT    (2 * Tt * 4)              // 1024
#define OFF_RED  (OFF_XT + SZ_XT)
#define SZ_RED   (16 * 4)
#define OFF_MB   (OFF_RED + SZ_RED)
#define SZ_MB    (8 * 8)
#define SMEM_TOTAL (OFF_MB + SZ_MB)        // 79744

typedef unsigned long long u64;

__device__ __forceinline__ uint32_t my_cluster_rank() {
    uint32_t r; asm("mov.u32 %0, %%cluster_ctarank;" : "=r"(r)); return r;
}
__device__ __forceinline__ void cluster_sync_() {
    asm volatile("barrier.cluster.arrive.aligned;" ::: "memory");
    asm volatile("barrier.cluster.wait.aligned;" ::: "memory");
}
__device__ __forceinline__ uint32_t mapa_u32(uint32_t laddr, uint32_t rank) {
    uint32_t r;
    asm("mapa.shared::cluster.u32 %0, %1, %2;" : "=r"(r) : "r"(laddr), "r"(rank));
    return r;
}
__device__ __forceinline__ void st_remote(uint32_t addr, float v) {
    asm volatile("st.shared::cluster.f32 [%0], %1;" :: "r"(addr), "f"(v) : "memory");
}
__device__ __forceinline__ void mb_init(uint32_t addr, uint32_t count) {
    asm volatile("mbarrier.init.shared.b64 [%0], %1;" :: "r"(addr), "r"(count) : "memory");
}
__device__ __forceinline__ void mb_arrive_remote(uint32_t raddr) {
    asm volatile("mbarrier.arrive.release.cluster.shared::cluster.b64 _, [%0];"
                 :: "r"(raddr) : "memory");
}
__device__ __forceinline__ void mb_wait(uint32_t addr, uint32_t parity) {
    uint32_t done;
    asm volatile(
        "{\n\t.reg .pred p;\n\t"
        "mbarrier.try_wait.parity.acquire.cluster.shared::cta.b64 p, [%1], %2;\n\t"
        "selp.b32 %0, 1, 0, p;\n\t}"
        : "=r"(done) : "r"(addr), "r"(parity) : "memory");
    while (!done) {
        asm volatile(
            "{\n\t.reg .pred p;\n\t"
            "mbarrier.try_wait.parity.acquire.cluster.shared::cta.b64 p, [%1], %2, 0x989680;\n\t"
            "selp.b32 %0, 1, 0, p;\n\t}"
            : "=r"(done) : "r"(addr), "r"(parity) : "memory");
    }
}
__device__ __forceinline__ float tanh_ap(float x) {
    float y; asm("tanh.approx.f32 %0, %1;" : "=f"(y) : "f"(x)); return y;
}
__device__ __forceinline__ float grp4_sum(float v) {
    v += __shfl_xor_sync(0xffffffffu, v, 1);
    v += __shfl_xor_sync(0xffffffffu, v, 2);
    return v;
}

// Dot over this thread's 64 d's: sum yin[d] * (alpha[d]*h[d] + w[d]) for its column.
__device__ __forceinline__ float dot_step(const float* __restrict__ yinp,
                                          const uint2* __restrict__ wthr,
                                          const __half2 (&a2)[32], const __half2 (&h2)[32]) {
    float s0 = 0.f, s1 = 0.f, s2 = 0.f, s3 = 0.f;
#pragma unroll
    for (int i = 0; i < 16; i++) {
        uint2 wv = wthr[i * NTHREADS];
        __half2 wlo = *reinterpret_cast<__half2*>(&wv.x);
        __half2 whi = *reinterpret_cast<__half2*>(&wv.y);
        float4 yv = *reinterpret_cast<const float4*>(yinp + 4 * i);
        float2 f0 = __half22float2(__hfma2(a2[2 * i],     h2[2 * i],     wlo));
        float2 f1 = __half22float2(__hfma2(a2[2 * i + 1], h2[2 * i + 1], whi));
        s0 = fmaf(yv.x, f0.x, s0); s1 = fmaf(yv.y, f0.y, s1);
        s2 = fmaf(yv.z, f1.x, s2); s3 = fmaf(yv.w, f1.y, s3);
    }
    return (s0 + s1) + (s2 + s3);
}

__device__ __forceinline__ void hebb_step(__half2 (&h2)[32], const float* __restrict__ yinp,
                                          float ey, __half2 om2) {
    __half2 ey2 = __float2half2_rn(ey);
#pragma unroll
    for (int i = 0; i < 16; i++) {
        float4 yv = *reinterpret_cast<const float4*>(yinp + 4 * i);
        __half2 y01 = __floats2half2_rn(yv.x, yv.y);
        __half2 y23 = __floats2half2_rn(yv.z, yv.w);
        h2[2 * i]     = __hfma2(h2[2 * i],     om2, __hmul2(y01, ey2));
        h2[2 * i + 1] = __hfma2(h2[2 * i + 1], om2, __hmul2(y23, ey2));
    }
}

__global__ void __launch_bounds__(NTHREADS, 1) __cluster_dims__(4, 1, 1)
plastic_kernel(const int* __restrict__ x, const float* __restrict__ emb,
               const float* __restrict__ ws, const float* __restrict__ alphas,
               const float* __restrict__ etas, float* __restrict__ out)
{
    extern __shared__ __align__(16) char smem_raw[];
    uint2* w4     = reinterpret_cast<uint2*>(smem_raw + OFF_W);     // [16][512]
    float* ybuf   = reinterpret_cast<float*>(smem_raw + OFF_YB);    // [2][4][YROW]
    float* y0h    = reinterpret_cast<float*>(smem_raw + OFF_Y0H);   // [2][4][128]
    int*   xtok   = reinterpret_cast<int*>(smem_raw + OFF_XT);      // [2][128]
    float* redbuf = reinterpret_cast<float*>(smem_raw + OFF_RED);   // [2][8]
    const uint32_t sbase = (uint32_t)__cvta_generic_to_shared(smem_raw);

    const int tid     = threadIdx.x;
    const int cluster = blockIdx.x >> 2;
    const int rank    = (int)my_cluster_rank();
    const int layer   = rank >> 1;
    const int half    = rank & 1;
    const int col_off = half * HCOLS;
    const int partner = rank ^ 1;
    const int col     = tid >> 2;
    const int colg    = col_off + col;
    const int dgrp    = tid & 3;
    const int wid     = tid >> 5, lane = tid & 31;
    const int pcol    = colg + (colg >> 6) * 8;      // padded ybuf index
    const int ptid    = tid + (tid >> 6) * 8;        // padded index for softmax read

#define MB_ADDR(b, s) (sbase + OFF_MB + (uint32_t)(((b) * 4 + (s)) * 8))
#define YB_SLOT(b, s) (ybuf + ((b) * 4 + (s)) * YROW)
#define Y0H_SLOT(b, s) (y0h + ((b) * 4 + (s)) * HCOLS)

    // ---- init ----
    for (int i = tid; i < 2 * 4 * YROW; i += NTHREADS) ybuf[i] = 0.f;
    for (int i = tid; i < 2 * 4 * HCOLS; i += NTHREADS) y0h[i] = 0.f;
    for (int i = tid; i < 2 * Tt; i += NTHREADS)
        xtok[i] = x[(cluster * 2 + (i >> 7)) * Tt + (i & 127)];
    if (tid == 0)
        for (int k = 0; k < 8; k++) mb_init(sbase + OFF_MB + 8u * k, 2);
    __syncthreads();

    const float eta = etas[layer];
    const __half2 om2 = __float2half2_rn(1.0f - eta);

    __half2 a2[32], h2a[32], h2b[32];
#pragma unroll
    for (int i = 0; i < 32; i++) { h2a[i] = __float2half2_rn(0.f); h2b[i] = h2a[i]; }

    // ---- stage alpha (fp16) through the w4 region, pull into regs ----
    const float* asrc = alphas + (size_t)layer * Dd * Dd;
    for (int idx = tid; idx < Dd * HCOLS; idx += NTHREADS) {
        int d = idx >> 7, c = idx & 127;
        __half v = __float2half(asrc[(size_t)d * Dd + col_off + c]);
        int o = c * 4 + (d >> 6), j = (d & 63) >> 2, k = d & 3;
        reinterpret_cast<__half*>(&w4[j * NTHREADS + o])[k] = v;
    }
    __syncthreads();
#pragma unroll
    for (int j = 0; j < 16; j++) {
        uint2 v = w4[j * NTHREADS + tid];
        a2[2 * j]     = *reinterpret_cast<__half2*>(&v.x);
        a2[2 * j + 1] = *reinterpret_cast<__half2*>(&v.y);
    }
    __syncthreads();

    // ---- load w (fp16) into the same layout, kept in smem ----
    const float* wsrc = ws + (size_t)layer * Dd * Dd;
    for (int idx = tid; idx < Dd * HCOLS; idx += NTHREADS) {
        int d = idx >> 7, c = idx & 127;
        __half v = __float2half(wsrc[(size_t)d * Dd + col_off + c]);
        int o = c * 4 + (d >> 6), j = (d & 63) >> 2, k = d & 3;
        reinterpret_cast<__half*>(&w4[j * NTHREADS + o])[k] = v;
    }
    __syncthreads();

    // ---- peer deltas ----
    const uint32_t del_partner = mapa_u32(sbase, (uint32_t)partner) - sbase;
    const uint32_t del_inter   = (layer == 0)
        ? (mapa_u32(sbase, (uint32_t)(rank + 2)) - sbase)
        : (mapa_u32(sbase, (uint32_t)(rank - 2)) - sbase);

    cluster_sync_();   // everyone initialized before any arrive/store

    // ---- virtual startup arrives ----
    if (tid == 0) {
        mb_arrive_remote(MB_ADDR(0, 0) + del_partner);
        mb_arrive_remote(MB_ADDR(1, 0) + del_partner);
    }
    if (tid == 32 && layer == 1) {   // 4 credits per batch to my L0
#pragma unroll
        for (int s = 0; s < 4; s++) {
            mb_arrive_remote(MB_ADDR(0, s) + del_inter);
            mb_arrive_remote(MB_ADDR(1, s) + del_inter);
        }
    }

    float* const outB0 = out + (size_t)(cluster * 2 + 0) * Tt * Dd;
    float* const outB1 = out + (size_t)(cluster * 2 + 1) * Tt * Dd;
    const uint2* wthr = w4 + tid;

    float embreg0 = 0.f, embreg1 = 0.f;
    if (layer == 0) {
        embreg0 = __ldg(&emb[(size_t)xtok[0] * Dd + colg]);
        embreg1 = __ldg(&emb[(size_t)xtok[Tt] * Dd + colg]);
    }

    for (int t = 0; t < Tt; ++t) {
        const int sc = t & 3, sp = (t + 3) & 3;
        const uint32_t par = (uint32_t)((t >> 2) & 1);

#define STEP_BATCH(B, H2, EMBREG, OUTB)                                          \
        {                                                                        \
            mb_wait(MB_ADDR(B, sc), par);                                        \
            const float* yinp = YB_SLOT(B, sp) + dgrp * 72;                      \
            float acc = grp4_sum(dot_step(yinp, wthr, a2, H2));                  \
            float inp = (layer == 0) ? EMBREG : Y0H_SLOT(B, sc)[col];            \
            float y = tanh_ap(acc + inp);                                        \
            float* yb = YB_SLOT(B, sc);                                          \
            if (dgrp == 1) yb[pcol] = y;                                         \
            if (dgrp == 0)                                                       \
                st_remote((uint32_t)__cvta_generic_to_shared(yb + pcol)          \
                          + del_partner, y);                                     \
            if (dgrp == 2 && layer == 0)                                         \
                st_remote((uint32_t)__cvta_generic_to_shared(                    \
                              Y0H_SLOT(B, sc) + col) + del_inter, y);            \
            __syncthreads();                                                     \
            if (tid == 0)                                                        \
                mb_arrive_remote(MB_ADDR(B, (t + 1) & 3) + del_partner);         \
            if (tid == 32)                                                       \
                mb_arrive_remote(MB_ADDR(B, sc) + del_inter);                    \
            hebb_step(H2, yinp, eta * y, om2);                                   \
            if (layer == 0 && t + 1 < Tt)                                        \
                EMBREG = __ldg(&emb[(size_t)xtok[B * Tt + t + 1] * Dd + colg]);  \
        }

        STEP_BATCH(0, h2a, embreg0, outB0)
        STEP_BATCH(1, h2b, embreg1, outB1)

        if (layer == 1 && t >= 1) {
            float ex0 = 0.f, ex1 = 0.f;
            if (tid < Dd) {
                float v0 = YB_SLOT(0, sp)[ptid];
                float v1 = YB_SLOT(1, sp)[ptid];
                ex0 = __expf(__fdividef(1.0f, 1.0f + __expf(-v0)));
                ex1 = __expf(__fdividef(1.0f, 1.0f + __expf(-v1)));
            }
            float w0 = ex0, w1 = ex1;
#pragma unroll
            for (int o = 16; o >= 1; o >>= 1) {
                w0 += __shfl_xor_sync(0xffffffffu, w0, o);
                w1 += __shfl_xor_sync(0xffffffffu, w1, o);
            }
            if (wid < 8 && lane == 0) { redbuf[wid] = w0; redbuf[8 + wid] = w1; }
            __syncthreads();
            float t0 = 0.f, t1 = 0.f;
#pragma unroll
            for (int k = 0; k < 8; k++) { t0 += redbuf[k]; t1 += redbuf[8 + k]; }
            if (tid >= col_off && tid < col_off + HCOLS) {
                outB0[(size_t)(t - 1) * Dd + tid] = __fdividef(ex0, t0);
                outB1[(size_t)(t - 1) * Dd + tid] = __fdividef(ex1, t1);
            }
        }
    }

    // ---- epilogue ----
    if (layer == 0) {
        if (tid == 32) {   // bonus arrives so L1's final slot-0 phase completes
            mb_arrive_remote(MB_ADDR(0, 0) + del_inter);
            mb_arrive_remote(MB_ADDR(1, 0) + del_inter);
        }
    } else {
        mb_wait(MB_ADDR(0, 0), 0u);
        mb_wait(MB_ADDR(1, 0), 0u);
        const int sp = 3;   // slot of y1(127)
        float ex0 = 0.f, ex1 = 0.f;
        if (tid < Dd) {
            float v0 = YB_SLOT(0, sp)[ptid];
            float v1 = YB_SLOT(1, sp)[ptid];
            ex0 = __expf(__fdividef(1.0f, 1.0f + __expf(-v0)));
            ex1 = __expf(__fdividef(1.0f, 1.0f + __expf(-v1)));
        }
        float w0 = ex0, w1 = ex1;
#pragma unroll
        for (int o = 16; o >= 1; o >>= 1) {
            w0 += __shfl_xor_sync(0xffffffffu, w0, o);
            w1 += __shfl_xor_sync(0xffffffffu, w1, o);
        }
        if (wid < 8 && lane == 0) { redbuf[wid] = w0; redbuf[8 + wid] = w1; }
        __syncthreads();
        float t0 = 0.f, t1 = 0.f;
#pragma unroll
        for (int k = 0; k < 8; k++) { t0 += redbuf[k]; t1 += redbuf[8 + k]; }
        if (tid >= col_off && tid < col_off + HCOLS) {
            outB0[(size_t)(Tt - 1) * Dd + tid] = __fdividef(ex0, t0);
            outB1[(size_t)(Tt - 1) * Dd + tid] = __fdividef(ex1, t1);
        }
    }

    cluster_sync_();
}

extern "C" void kernel_launch(void* const* d_in, const int* in_sizes, int n_in,
                              void* d_out, int out_size) {
    const int*   x      = (const int*)d_in[0];
    const float* emb    = (const float*)d_in[1];
    const float* ws     = (const float*)d_in[2];
    const float* alphas = (const float*)d_in[3];
    const float* etas   = (const float*)d_in[4];
    cudaFuncSetAttribute(plastic_kernel,
                         cudaFuncAttributeMaxDynamicSharedMemorySize, SMEM_TOTAL);
    plastic_kernel<<<(Bb / 2) * 4, NTHREADS, SMEM_TOTAL>>>(
        x, emb, ws, alphas, etas, (float*)d_out);
}

// round 8
// speedup vs baseline: 1.5845x; 1.1948x over previous
#include <cuda_runtime.h>
#include <cuda_fp16.h>
#include <cstdint>
#include <cstddef>

#define Bb 16
#define Tt 128
#define Dd 256
#define HCOLS 128
#define NTHREADS 512

// smem layout (bytes)
#define OFF_WA   0
#define SZ_WA    (16 * NTHREADS * 16)      // 131072: fp16 w+alpha interleaved uint4 rows
#define OFF_YB   (OFF_WA + SZ_WA)
#define YSLOT_H  320                        // halves per slot (4 chunks of 72 + pad)
#define SZ_YB    (2 * 4 * YSLOT_H * 2)      // 5120
#define OFF_Y0H  (OFF_YB + SZ_YB)
#define SZ_Y0H   (2 * 4 * HCOLS * 2)        // 2048
#define OFF_XT   (OFF_Y0H + SZ_Y0H)
#define SZ_XT    (2 * Tt * 4)               // 1024
#define OFF_RED  (OFF_XT + SZ_XT)
#define SZ_RED   (16 * 4)
#define OFF_MB   (OFF_RED + SZ_RED)
#define SZ_MB    (8 * 8)
#define SMEM_TOTAL (OFF_MB + SZ_MB)

__device__ __forceinline__ uint32_t my_cluster_rank() {
    uint32_t r; asm("mov.u32 %0, %%cluster_ctarank;" : "=r"(r)); return r;
}
__device__ __forceinline__ void cluster_sync_() {
    asm volatile("barrier.cluster.arrive.aligned;" ::: "memory");
    asm volatile("barrier.cluster.wait.aligned;" ::: "memory");
}
__device__ __forceinline__ uint32_t mapa_u32(uint32_t laddr, uint32_t rank) {
    uint32_t r;
    asm("mapa.shared::cluster.u32 %0, %1, %2;" : "=r"(r) : "r"(laddr), "r"(rank));
    return r;
}
__device__ __forceinline__ void st_remote_u16(uint32_t addr, __half v) {
    asm volatile("st.shared::cluster.u16 [%0], %1;"
                 :: "r"(addr), "h"(__half_as_ushort(v)) : "memory");
}
__device__ __forceinline__ void mb_init(uint32_t addr, uint32_t count) {
    asm volatile("mbarrier.init.shared.b64 [%0], %1;" :: "r"(addr), "r"(count) : "memory");
}
__device__ __forceinline__ void mb_arrive_remote(uint32_t raddr) {
    asm volatile("mbarrier.arrive.release.cluster.shared::cluster.b64 _, [%0];"
                 :: "r"(raddr) : "memory");
}
__device__ __forceinline__ void mb_wait(uint32_t addr, uint32_t parity) {
    uint32_t done;
    asm volatile(
        "{\n\t.reg .pred p;\n\t"
        "mbarrier.try_wait.parity.acquire.cluster.shared::cta.b64 p, [%1], %2;\n\t"
        "selp.b32 %0, 1, 0, p;\n\t}"
        : "=r"(done) : "r"(addr), "r"(parity) : "memory");
    while (!done) {
        asm volatile(
            "{\n\t.reg .pred p;\n\t"
            "mbarrier.try_wait.parity.acquire.cluster.shared::cta.b64 p, [%1], %2, 0x989680;\n\t"
            "selp.b32 %0, 1, 0, p;\n\t}"
            : "=r"(done) : "r"(addr), "r"(parity) : "memory");
    }
}
__device__ __forceinline__ float tanh_ap(float x) {
    float y; asm("tanh.approx.f32 %0, %1;" : "=f"(y) : "f"(x)); return y;
}
__device__ __forceinline__ float grp4_sum(float v) {
    v += __shfl_xor_sync(0xffffffffu, v, 1);
    v += __shfl_xor_sync(0xffffffffu, v, 2);
    return v;
}

__global__ void __launch_bounds__(NTHREADS, 1) __cluster_dims__(4, 1, 1)
plastic_kernel(const int* __restrict__ x, const float* __restrict__ emb,
               const float* __restrict__ ws, const float* __restrict__ alphas,
               const float* __restrict__ etas, float* __restrict__ out)
{
    extern __shared__ __align__(16) char smem_raw[];
    uint4*  wa     = reinterpret_cast<uint4*>(smem_raw + OFF_WA);    // [16][512]
    __half* ybuf   = reinterpret_cast<__half*>(smem_raw + OFF_YB);   // [2][4][YSLOT_H]
    __half* y0h    = reinterpret_cast<__half*>(smem_raw + OFF_Y0H);  // [2][4][128]
    int*    xtok   = reinterpret_cast<int*>(smem_raw + OFF_XT);      // [2][128]
    float*  redbuf = reinterpret_cast<float*>(smem_raw + OFF_RED);   // [16]
    const uint32_t sbase = (uint32_t)__cvta_generic_to_shared(smem_raw);

    const int tid     = threadIdx.x;
    const int cluster = blockIdx.x >> 2;
    const int rank    = (int)my_cluster_rank();
    const int layer   = rank >> 1;
    const int half_   = rank & 1;
    const int col_off = half_ * HCOLS;
    const int partner = rank ^ 1;
    const int col     = tid >> 2;            // 0..127
    const int colg    = col_off + col;
    const int dgrp    = tid & 3;             // 0..3, owns d in [dgrp*64, dgrp*64+64)
    const int wid     = tid >> 5, lane = tid & 31;
    const int pcol    = (colg >> 6) * 72 + (colg & 63);   // padded ybuf half-index
    const int ptid    = (tid >> 6) * 72 + (tid & 63);     // softmax read index

#define MB_ADDR(b, s)  (sbase + OFF_MB + (uint32_t)(((b) * 4 + (s)) * 8))
#define YB_SLOT(b, s)  (ybuf + ((b) * 4 + (s)) * YSLOT_H)
#define Y0H_SLOT(b, s) (y0h + ((b) * 4 + (s)) * HCOLS)

    // ---- init shared ----
    for (int i = tid; i < 2 * 4 * YSLOT_H; i += NTHREADS) ybuf[i] = __ushort_as_half(0);
    for (int i = tid; i < 2 * 4 * HCOLS; i += NTHREADS) y0h[i] = __ushort_as_half(0);
    for (int i = tid; i < 2 * Tt; i += NTHREADS)
        xtok[i] = x[(cluster * 2 + (i >> 7)) * Tt + (i & 127)];
    if (tid == 0)
        for (int k = 0; k < 8; k++) mb_init(sbase + OFF_MB + 8u * k, 2);
    __syncthreads();

    const float eta = etas[layer];
    const __half2 om2 = __float2half2_rn(1.0f - eta);

    __half2 h2a[32], h2b[32];
#pragma unroll
    for (int i = 0; i < 32; i++) { h2a[i] = __float2half2_rn(0.f); h2b[i] = h2a[i]; }

    // ---- stage w + alpha (fp16) into interleaved per-thread chunks ----
    // row 2j = w chunk j (8 halves/thread), row 2j+1 = alpha chunk j
    {
        const float* wsrc = ws     + (size_t)layer * Dd * Dd;
        const float* asrc = alphas + (size_t)layer * Dd * Dd;
        for (int idx = tid; idx < Dd * HCOLS; idx += NTHREADS) {
            int d = idx >> 7, c = idx & 127;
            int o = c * 4 + (d >> 6);          // owner thread
            int j = (d & 63) >> 3;             // chunk
            int k = d & 7;                     // half index
            float wv = wsrc[(size_t)d * Dd + col_off + c];
            float av = asrc[(size_t)d * Dd + col_off + c];
            reinterpret_cast<__half*>(&wa[(2 * j) * NTHREADS + o])[k]     = __float2half(wv);
            reinterpret_cast<__half*>(&wa[(2 * j + 1) * NTHREADS + o])[k] = __float2half(av);
        }
    }
    __syncthreads();

    // ---- peer deltas ----
    const uint32_t del_partner = mapa_u32(sbase, (uint32_t)partner) - sbase;
    const uint32_t del_inter   = (layer == 0)
        ? (mapa_u32(sbase, (uint32_t)(rank + 2)) - sbase)
        : (mapa_u32(sbase, (uint32_t)(rank - 2)) - sbase);

    cluster_sync_();   // everyone initialized before any arrive/store

    // ---- virtual startup arrives (same protocol as R7) ----
    if (tid == 0) {
        mb_arrive_remote(MB_ADDR(0, 0) + del_partner);
        mb_arrive_remote(MB_ADDR(1, 0) + del_partner);
    }
    if (tid == 32 && layer == 1) {
#pragma unroll
        for (int s = 0; s < 4; s++) {
            mb_arrive_remote(MB_ADDR(0, s) + del_inter);
            mb_arrive_remote(MB_ADDR(1, s) + del_inter);
        }
    }

    float* const outB0 = out + (size_t)(cluster * 2 + 0) * Tt * Dd;
    float* const outB1 = out + (size_t)(cluster * 2 + 1) * Tt * Dd;
    const uint4* wthr = wa + tid;

    float embreg0 = 0.f, embreg1 = 0.f;
    if (layer == 0) {
        embreg0 = __ldg(&emb[(size_t)xtok[0] * Dd + colg]);
        embreg1 = __ldg(&emb[(size_t)xtok[Tt] * Dd + colg]);
    }

    for (int t = 0; t < Tt; ++t) {
        const int sc = t & 3, sp = (t + 3) & 3;
        const uint32_t par = (uint32_t)((t >> 2) & 1);

#define STEP_BATCH(B, H2, EMBREG, OUTB)                                            \
        {                                                                          \
            mb_wait(MB_ADDR(B, sc), par);                                          \
            const uint4* yp = reinterpret_cast<const uint4*>(                      \
                YB_SLOT(B, sp) + dgrp * 72);                                       \
            __half2 yc[32];                                                        \
            __half2 acc0 = __float2half2_rn(0.f), acc1 = acc0;                     \
            __half2 acc2 = acc0, acc3 = acc0;                                      \
            _Pragma("unroll")                                                      \
            for (int j = 0; j < 8; j++) {                                          \
                uint4 wv = wthr[(2 * j) * NTHREADS];                               \
                uint4 av = wthr[(2 * j + 1) * NTHREADS];                           \
                uint4 yv = yp[j];                                                  \
                __half2 y0 = *reinterpret_cast<__half2*>(&yv.x);                   \
                __half2 y1 = *reinterpret_cast<__half2*>(&yv.y);                   \
                __half2 y2 = *reinterpret_cast<__half2*>(&yv.z);                   \
                __half2 y3 = *reinterpret_cast<__half2*>(&yv.w);                   \
                yc[4 * j] = y0; yc[4 * j + 1] = y1;                                \
                yc[4 * j + 2] = y2; yc[4 * j + 3] = y3;                            \
                acc0 = __hfma2(y0, __hfma2(*reinterpret_cast<__half2*>(&av.x),     \
                                  H2[4 * j],     *reinterpret_cast<__half2*>(&wv.x)), acc0); \
                acc1 = __hfma2(y1, __hfma2(*reinterpret_cast<__half2*>(&av.y),     \
                                  H2[4 * j + 1], *reinterpret_cast<__half2*>(&wv.y)), acc1); \
                acc2 = __hfma2(y2, __hfma2(*reinterpret_cast<__half2*>(&av.z),     \
                                  H2[4 * j + 2], *reinterpret_cast<__half2*>(&wv.z)), acc2); \
                acc3 = __hfma2(y3, __hfma2(*reinterpret_cast<__half2*>(&av.w),     \
                                  H2[4 * j + 3], *reinterpret_cast<__half2*>(&wv.w)), acc3); \
            }                                                                      \
            float2 f0 = __half22float2(__hadd2(acc0, acc1));                       \
            float2 f1 = __half22float2(__hadd2(acc2, acc3));                       \
            float acc = grp4_sum((f0.x + f0.y) + (f1.x + f1.y));                   \
            float inp = (layer == 0) ? EMBREG                                      \
                                     : __half2float(Y0H_SLOT(B, sc)[col]);         \
            float y = tanh_ap(acc + inp);                                          \
            __half yh = __float2half(y);                                           \
            __half* yb = YB_SLOT(B, sc);                                           \
            if (dgrp == 1) yb[pcol] = yh;                                          \
            if (dgrp == 0)                                                         \
                st_remote_u16((uint32_t)__cvta_generic_to_shared(yb + pcol)        \
                              + del_partner, yh);                                  \
            if (dgrp == 2 && layer == 0)                                           \
                st_remote_u16((uint32_t)__cvta_generic_to_shared(                  \
                                  Y0H_SLOT(B, sc) + col) + del_inter, yh);         \
            __syncthreads();                                                       \
            if (tid == 0)                                                          \
                mb_arrive_remote(MB_ADDR(B, (t + 1) & 3) + del_partner);           \
            if (tid == 32)                                                         \
                mb_arrive_remote(MB_ADDR(B, sc) + del_inter);                      \
            {                                                                      \
                __half2 ey2 = __float2half2_rn(eta * y);                           \
                _Pragma("unroll")                                                  \
                for (int i = 0; i < 32; i++)                                       \
                    H2[i] = __hfma2(H2[i], om2, __hmul2(yc[i], ey2));              \
            }                                                                      \
            if (layer == 0 && t + 1 < Tt)                                          \
                EMBREG = __ldg(&emb[(size_t)xtok[B * Tt + t + 1] * Dd + colg]);    \
        }

        STEP_BATCH(0, h2a, embreg0, outB0)
        STEP_BATCH(1, h2b, embreg1, outB1)

        if (layer == 1 && t >= 1) {
            float ex0 = 0.f, ex1 = 0.f;
            if (tid < Dd) {
                float v0 = __half2float(YB_SLOT(0, sp)[ptid]);
                float v1 = __half2float(YB_SLOT(1, sp)[ptid]);
                ex0 = __expf(__fdividef(1.0f, 1.0f + __expf(-v0)));
                ex1 = __expf(__fdividef(1.0f, 1.0f + __expf(-v1)));
            }
            float w0 = ex0, w1 = ex1;
#pragma unroll
            for (int o = 16; o >= 1; o >>= 1) {
                w0 += __shfl_xor_sync(0xffffffffu, w0, o);
                w1 += __shfl_xor_sync(0xffffffffu, w1, o);
            }
            if (wid < 8 && lane == 0) { redbuf[wid] = w0; redbuf[8 + wid] = w1; }
            __syncthreads();
            float t0 = 0.f, t1 = 0.f;
#pragma unroll
            for (int k = 0; k < 8; k++) { t0 += redbuf[k]; t1 += redbuf[8 + k]; }
            if (tid >= col_off && tid < col_off + HCOLS) {
                outB0[(size_t)(t - 1) * Dd + tid] = __fdividef(ex0, t0);
                outB1[(size_t)(t - 1) * Dd + tid] = __fdividef(ex1, t1);
            }
        }
    }

    // ---- epilogue ----
    if (layer == 0) {
        if (tid == 32) {
            mb_arrive_remote(MB_ADDR(0, 0) + del_inter);
            mb_arrive_remote(MB_ADDR(1, 0) + del_inter);
        }
    } else {
        mb_wait(MB_ADDR(0, 0), 0u);
        mb_wait(MB_ADDR(1, 0), 0u);
        const int sp = 3;
        float ex0 = 0.f, ex1 = 0.f;
        if (tid < Dd) {
            float v0 = __half2float(YB_SLOT(0, sp)[ptid]);
            float v1 = __half2float(YB_SLOT(1, sp)[ptid]);
            ex0 = __expf(__fdividef(1.0f, 1.0f + __expf(-v0)));
            ex1 = __expf(__fdividef(1.0f, 1.0f + __expf(-v1)));
        }
        float w0 = ex0, w1 = ex1;
#pragma unroll
        for (int o = 16; o >= 1; o >>= 1) {
            w0 += __shfl_xor_sync(0xffffffffu, w0, o);
            w1 += __shfl_xor_sync(0xffffffffu, w1, o);
        }
        if (wid < 8 && lane == 0) { redbuf[wid] = w0; redbuf[8 + wid] = w1; }
        __syncthreads();
        float t0 = 0.f, t1 = 0.f;
#pragma unroll
        for (int k = 0; k < 8; k++) { t0 += redbuf[k]; t1 += redbuf[8 + k]; }
        if (tid >= col_off && tid < col_off + HCOLS) {
            outB0[(size_t)(Tt - 1) * Dd + tid] = __fdividef(ex0, t0);
            outB1[(size_t)(Tt - 1) * Dd + tid] = __fdividef(ex1, t1);
        }
    }

    cluster_sync_();
}

extern "C" void kernel_launch(void* const* d_in, const int* in_sizes, int n_in,
                              void* d_out, int out_size) {
    const int*   x      = (const int*)d_in[0];
    const float* emb    = (const float*)d_in[1];
    const float* ws     = (const float*)d_in[2];
    const float* alphas = (const float*)d_in[3];
    const float* etas   = (const float*)d_in[4];
    cudaFuncSetAttribute(plastic_kernel,
                         cudaFuncAttributeMaxDynamicSharedMemorySize, SMEM_TOTAL);
    plastic_kernel<<<(Bb / 2) * 4, NTHREADS, SMEM_TOTAL>>>(
        x, emb, ws, alphas, etas, (float*)d_out);
}